// round 3
// baseline (speedup 1.0000x reference)
#include <cuda_runtime.h>
#include <math.h>

// Shapes fixed by the reference:
//   x: (2, 32768, 3) f32; verts: (2, 8192, 3) f32 subsampled ::8 -> M=1024
//   out: (2, 32768, 3) f32;  inv_sigma2 = 4
#define B_    2
#define N_    32768
#define D_    3
#define MFULL 8192
#define M_    1024
#define SUB_  8
#define LUT_  131072                 // fine buckets per (b,d) = 2^17
#define LUTS_ (LUT_ + 4)
#define EXPB_ 513                    // ceil((LUT_+1)/256) expansion blocks per (b,d)

// Stage 1 products (exact fp64 scans over sorted dv):
__device__ float   g_sdv[B_][D_][M_];            // sorted dv
__device__ float2  g_rngd[B_][D_];               // {min dv, max dv} per (b,d)
__device__ double2 g_tab[B_][D_][M_ + 1][2];     // [k][0]={pA,pMA} excl prefix of e^{4dv}, mv e^{4dv}
                                                 // [k][1]={sB,sMB} incl suffix of e^{-4dv}, mv e^{-4dv}
// Stage 2 product: fine table at bucket edges e_q, locally rescaled to fp32 range:
//   {P,PM,S,SM}(q) = {pA*e^{-4e_q}, pMA*e^{-4e_q}, sB*e^{+4e_q}, sMB*e^{+4e_q}} at k=count(dv<e_q)
__device__ float4  g_ftab[B_][D_][LUTS_];

__device__ __forceinline__ void xstage(float& key, float& val, int t, int k, int j) {
    const float pk = __shfl_xor_sync(0xffffffffu, key, j);
    const float pv = __shfl_xor_sync(0xffffffffu, val, j);
    const bool up    = ((t & k) == 0);
    const bool lower = ((t & j) == 0);
    const bool take  = (lower == up) ? (pk < key) : (pk > key);
    if (take) { key = pk; val = pv; }
}

// ---------------------------------------------------------------------------
// Kernel 1: per (b,d) sort 1024 (dv,mv) + fp64 scan tables.  grid=6, block=1024
// ---------------------------------------------------------------------------
__global__ void __launch_bounds__(M_, 1)
build_tables(const float* __restrict__ dv_in, const float* __restrict__ mv_in) {
    const int b = blockIdx.x / D_;
    const int d = blockIdx.x % D_;
    const int t = threadIdx.x, lane = t & 31, w = t >> 5;

    __shared__ float  sk[2][M_];
    __shared__ float  sv[2][M_];
    __shared__ double s_chp[2][32];
    __shared__ double s_chs[2][32];

    const int src = (b * MFULL + t * SUB_) * D_ + d;
    float key = dv_in[src];
    float val = mv_in[src];

    // Bitonic sort: k=2..32 in registers via shuffles.
    #pragma unroll
    for (int k = 2; k <= 32; k <<= 1)
        #pragma unroll
        for (int j = k >> 1; j >= 1; j >>= 1)
            xstage(key, val, t, k, j);

    // k=64..1024: j>=32 via double-buffered smem (1 bar/stage), j<=16 via shfl.
    int p = 0;
    for (int k = 64; k <= M_; k <<= 1) {
        for (int j = k >> 1; j >= 32; j >>= 1) {
            sk[p][t] = key; sv[p][t] = val;
            __syncthreads();
            const float pk = sk[p][t ^ j];
            const float pv = sv[p][t ^ j];
            const bool up = ((t & k) == 0), lower = ((t & j) == 0);
            const bool take = (lower == up) ? (pk < key) : (pk > key);
            if (take) { key = pk; val = pv; }
            p ^= 1;
        }
        #pragma unroll
        for (int j = 16; j >= 1; j >>= 1) xstage(key, val, t, k, j);
    }

    g_sdv[b][d][t] = key;
    if (t == 0)      g_rngd[b][d].x = key;
    if (t == M_ - 1) g_rngd[b][d].y = key;

    // Terms: expf (1e-7 rel) + fp64 accumulation.
    const float apf = expf( 4.0f * key);
    const float amf = expf(-4.0f * key);
    const double vd = (double)val;
    const double v0 = (double)apf;
    const double v1 = vd * (double)apf;
    const double v2 = (double)amf;
    const double v3 = vd * (double)amf;

    // Warp Kogge-Stone: inclusive prefix (v0,v1), inclusive suffix (v2,v3).
    double i0 = v0, i1 = v1, i2 = v2, i3 = v3;
    #pragma unroll
    for (int s = 1; s < 32; s <<= 1) {
        double a = __shfl_up_sync(0xffffffffu, i0, s);   if (lane >= s)     i0 += a;
        double bq = __shfl_up_sync(0xffffffffu, i1, s);  if (lane >= s)     i1 += bq;
        double c = __shfl_down_sync(0xffffffffu, i2, s); if (lane < 32 - s) i2 += c;
        double e = __shfl_down_sync(0xffffffffu, i3, s); if (lane < 32 - s) i3 += e;
    }
    if (lane == 31) { s_chp[0][w] = i0; s_chp[1][w] = i1; }
    if (lane == 0)  { s_chs[0][w] = i2; s_chs[1][w] = i3; }
    __syncthreads();

    // Chunk-level carries.
    if (w < 2) {
        double ic = s_chp[w][lane];
        #pragma unroll
        for (int s = 1; s < 32; s <<= 1) { double a = __shfl_up_sync(0xffffffffu, ic, s); if (lane >= s) ic += a; }
        double ex = __shfl_up_sync(0xffffffffu, ic, 1);
        if (lane == 0) ex = 0.0;
        s_chp[w][lane] = ex;
    } else if (w < 4) {
        const int q = w - 2;
        double ic = s_chs[q][lane];
        #pragma unroll
        for (int s = 1; s < 32; s <<= 1) { double a = __shfl_down_sync(0xffffffffu, ic, s); if (lane < 32 - s) ic += a; }
        double ca = __shfl_down_sync(0xffffffffu, ic, 1);
        if (lane == 31) ca = 0.0;
        s_chs[q][lane] = ca;
    }
    __syncthreads();

    double e0 = __shfl_up_sync(0xffffffffu, i0, 1); if (lane == 0) e0 = 0.0;
    double e1 = __shfl_up_sync(0xffffffffu, i1, 1); if (lane == 0) e1 = 0.0;
    e0 += s_chp[0][w];
    e1 += s_chp[1][w];
    const double sf2 = i2 + s_chs[0][w];
    const double sf3 = i3 + s_chs[1][w];

    g_tab[b][d][t][0] = make_double2(e0, e1);
    g_tab[b][d][t][1] = make_double2(sf2, sf3);
    if (t == M_ - 1) g_tab[b][d][M_][0] = make_double2(e0 + v0, e1 + v1);
    if (t == 0)      g_tab[b][d][M_][1] = make_double2(0.0, 0.0);
}

// fp64 * fp32 -> fp32 without the 1:64 fp64 mul pipe: hi/lo split.
__device__ __forceinline__ float dmulf(double a, float s) {
    const float h = (float)a;
    const float l = (float)(a - (double)h);
    return fmaf(h, s, l * s);
}

// ---------------------------------------------------------------------------
// Kernel 2: expand fp64 k-tables into the fine fp32 bucket table.
// grid = 6 * 513 blocks of 256; block handles 256 consecutive buckets of one (b,d).
// ---------------------------------------------------------------------------
__global__ void __launch_bounds__(256)
expand_kernel() {
    const int bd    = blockIdx.x / EXPB_;
    const int chunk = blockIdx.x % EXPB_;
    const int b = bd / D_, d = bd % D_;
    const int tid = threadIdx.x;

    __shared__ float s_dv[M_];
    #pragma unroll
    for (int i = tid; i < M_; i += 256) s_dv[i] = g_sdv[b][d][i];
    __syncthreads();

    const int q = chunk * 256 + tid;
    if (q > LUT_) return;

    // Per-b common bucket geometry (same formula as eval — bitwise identical).
    const float2 r0 = g_rngd[b][0], r1 = g_rngd[b][1], r2 = g_rngd[b][2];
    const float lo = fminf(r0.x, fminf(r1.x, r2.x));
    const float hi = fmaxf(r0.y, fmaxf(r1.y, r2.y));
    const float span = (hi - lo) * 1.0001f + 1e-20f;   // margin: e_LUT > hi strictly
    const float w = span * (1.0f / (float)LUT_);

    const float eq = fmaf((float)q, w, lo);

    // k = count(dv < eq) over sorted smem array.
    int k;
    if (s_dv[M_ - 1] < eq) {
        k = M_;
    } else {
        k = 0;
        #pragma unroll
        for (int s = M_ / 2; s >= 1; s >>= 1)
            if (s_dv[k + s - 1] < eq) k += s;
    }

    const double2 tp = g_tab[b][d][k][0];
    const double2 ts = g_tab[b][d][k][1];
    const float sm = expf(-4.0f * eq);   // <= e^{14.6}, fp32-safe
    const float sp = expf( 4.0f * eq);

    float4 o;
    o.x = dmulf(tp.x, sm);   // P
    o.y = dmulf(tp.y, sm);   // PM
    o.z = dmulf(ts.x, sp);   // S
    o.w = dmulf(ts.y, sp);   // SM
    g_ftab[b][d][q] = o;
}

// ---------------------------------------------------------------------------
// Kernel 3: eval. 4 outputs/thread, 1 LDG.128 table fetch per output,
// no smem, no search. grid = 192 blocks of 256.
// ---------------------------------------------------------------------------
__global__ void __launch_bounds__(256)
eval_kernel(const float4* __restrict__ x4, float4* __restrict__ out4) {
    const int tid4 = blockIdx.x * 256 + threadIdx.x;
    const int f0 = tid4 * 4;
    const int b = f0 / (N_ * D_);

    const float2 r0 = g_rngd[b][0], r1 = g_rngd[b][1], r2 = g_rngd[b][2];
    const float lo = fminf(r0.x, fminf(r1.x, r2.x));
    const float hi = fmaxf(r0.y, fmaxf(r1.y, r2.y));
    const float span = (hi - lo) * 1.0001f + 1e-20f;
    const float w    = span * (1.0f / (float)LUT_);
    const float invw = (float)LUT_ / span;

    const float4 xv = x4[tid4];
    const float xs[4] = {xv.x, xv.y, xv.z, xv.w};
    const int d0 = f0 % 3;

    float res[4];
    #pragma unroll
    for (int i = 0; i < 4; i++) {
        int d = d0 + i; if (d >= 3) d -= 3; if (d >= 3) d -= 3;
        const float x = xs[i];
        const float fq = (x - lo) * invw;
        const int qi = (int)fq;                       // trunc toward 0
        const int q = qi < 0 ? 0 : (qi > LUT_ ? LUT_ : qi);

        const float4 tb = __ldg(&g_ftab[b][d][q]);
        const float t = x - fmaf((float)q, w, lo);    // in [0,w) off clamp path
        const float arg = -8.0f * t;
        // e = e^{-8t}: 1st-order poly valid when |arg| <~ 1e-3 (unclamped);
        // exact exp on the (rare, pure-one-sided => exact-split) clamp path.
        const bool fast = (qi >= 0) & (qi < LUT_);
        const float e = fast ? (1.0f + arg) : __expf(arg);

        res[i] = __fdividef(fmaf(e, tb.y, tb.w), fmaf(e, tb.x, tb.z));
    }

    float4 ov; ov.x = res[0]; ov.y = res[1]; ov.z = res[2]; ov.w = res[3];
    out4[tid4] = ov;
}

// ---------------------------------------------------------------------------
extern "C" void kernel_launch(void* const* d_in, const int* in_sizes, int n_in,
                              void* d_out, int out_size) {
    const float* x  = (const float*)d_in[0];
    const float* dv = (const float*)d_in[1];
    const float* mv = (const float*)d_in[2];

    build_tables<<<B_ * D_, M_>>>(dv, mv);
    expand_kernel<<<B_ * D_ * EXPB_, 256>>>();
    eval_kernel<<<(B_ * N_ * D_) / (256 * 4), 256>>>((const float4*)x, (float4*)d_out);
}

// round 4
// speedup vs baseline: 1.3651x; 1.3651x over previous
#include <cuda_runtime.h>
#include <math.h>

// Shapes fixed by the reference:
//   x: (2, 32768, 3) f32; verts: (2, 8192, 3) f32 subsampled ::8 -> M=1024
//   out: (2, 32768, 3) f32;  inv_sigma2 = 4
#define B_    2
#define N_    32768
#define D_    3
#define MFULL 8192
#define M_    1024
#define SUB_  8
#define SLICES_ 8                    // rank kernel: 8 x 128-thread slices per (b,d)
#define LUT_  32768                  // fine buckets per (b,d)
#define LUTS_ (LUT_ + 4)
#define EXPB_ ((LUT_ + 256) / 256)   // 129 expansion blocks per (b,d)

// Stage products:
__device__ float   g_skey[B_][D_][M_];           // sorted dv
__device__ float   g_sval[B_][D_][M_];           // mv permuted to sorted order
__device__ float2  g_rngd[B_][D_];               // {min dv, max dv}
__device__ double2 g_tab[B_][D_][M_ + 1][2];     // [k][0]={pA,pMA} excl prefix of e^{4dv}, mv e^{4dv}
                                                 // [k][1]={sB,sMB} incl suffix of e^{-4dv}, mv e^{-4dv}
// Fine table at bucket edges e_q, locally rescaled to O(1..1e3) fp32:
//   {P,PM,S,SM}(q) = {pA,pMA}*e^{-4e_q}, {sB,sMB}*e^{+4e_q} at k=count(dv<e_q)
__device__ float4  g_ftab[B_][D_][LUTS_];

// ---------------------------------------------------------------------------
// Kernel 1: rank-by-counting sort. grid = 6*SLICES_, block = 128.
// Each block stages all 1024 keys of its (b,d); each thread ranks one element
// and scatters (key,val) to g_skey/g_sval[rank]. Stable via index tie-break.
// ---------------------------------------------------------------------------
__global__ void __launch_bounds__(128)
rank_kernel(const float* __restrict__ dv_in, const float* __restrict__ mv_in) {
    const int bd = blockIdx.x / SLICES_, slice = blockIdx.x % SLICES_;
    const int b = bd / D_, d = bd % D_;

    __shared__ __align__(16) float s_key[M_];
    for (int i = threadIdx.x; i < M_; i += 128)
        s_key[i] = dv_in[(b * MFULL + i * SUB_) * D_ + d];
    __syncthreads();

    const int i = slice * 128 + threadIdx.x;
    const float ki = s_key[i];

    int r = 0;
    const float4* k4 = (const float4*)s_key;
    #pragma unroll 8
    for (int j4 = 0; j4 < M_ / 4; j4++) {
        const float4 kk = k4[j4];
        const int j = j4 * 4;
        r += (kk.x < ki) || (kk.x == ki && (j + 0) < i);
        r += (kk.y < ki) || (kk.y == ki && (j + 1) < i);
        r += (kk.z < ki) || (kk.z == ki && (j + 2) < i);
        r += (kk.w < ki) || (kk.w == ki && (j + 3) < i);
    }

    g_skey[b][d][r] = ki;
    g_sval[b][d][r] = mv_in[(b * MFULL + i * SUB_) * D_ + d];
    if (r == 0)      g_rngd[b][d].x = ki;
    if (r == M_ - 1) g_rngd[b][d].y = ki;
}

// ---------------------------------------------------------------------------
// Kernel 2: fp64 scan tables over sorted order. grid = 6, block = 1024.
// ---------------------------------------------------------------------------
__global__ void __launch_bounds__(M_, 1)
scan_kernel() {
    const int b = blockIdx.x / D_;
    const int d = blockIdx.x % D_;
    const int t = threadIdx.x, lane = t & 31, w = t >> 5;

    __shared__ double s_chp[2][32];
    __shared__ double s_chs[2][32];

    const float key = g_skey[b][d][t];
    const float val = g_sval[b][d][t];

    // Terms: expf (1e-7 rel) + fp64 accumulation.
    const float apf = expf( 4.0f * key);
    const float amf = expf(-4.0f * key);
    const double vd = (double)val;
    const double v0 = (double)apf;
    const double v1 = vd * (double)apf;
    const double v2 = (double)amf;
    const double v3 = vd * (double)amf;

    // Warp Kogge-Stone: inclusive prefix (v0,v1), inclusive suffix (v2,v3).
    double i0 = v0, i1 = v1, i2 = v2, i3 = v3;
    #pragma unroll
    for (int s = 1; s < 32; s <<= 1) {
        double a = __shfl_up_sync(0xffffffffu, i0, s);   if (lane >= s)     i0 += a;
        double bq = __shfl_up_sync(0xffffffffu, i1, s);  if (lane >= s)     i1 += bq;
        double c = __shfl_down_sync(0xffffffffu, i2, s); if (lane < 32 - s) i2 += c;
        double e = __shfl_down_sync(0xffffffffu, i3, s); if (lane < 32 - s) i3 += e;
    }
    if (lane == 31) { s_chp[0][w] = i0; s_chp[1][w] = i1; }
    if (lane == 0)  { s_chs[0][w] = i2; s_chs[1][w] = i3; }
    __syncthreads();

    // Chunk-level carries (warps 0,1 prefix; 2,3 suffix).
    if (w < 2) {
        double ic = s_chp[w][lane];
        #pragma unroll
        for (int s = 1; s < 32; s <<= 1) { double a = __shfl_up_sync(0xffffffffu, ic, s); if (lane >= s) ic += a; }
        double ex = __shfl_up_sync(0xffffffffu, ic, 1);
        if (lane == 0) ex = 0.0;
        s_chp[w][lane] = ex;
    } else if (w < 4) {
        const int q = w - 2;
        double ic = s_chs[q][lane];
        #pragma unroll
        for (int s = 1; s < 32; s <<= 1) { double a = __shfl_down_sync(0xffffffffu, ic, s); if (lane < 32 - s) ic += a; }
        double ca = __shfl_down_sync(0xffffffffu, ic, 1);
        if (lane == 31) ca = 0.0;
        s_chs[q][lane] = ca;
    }
    __syncthreads();

    double e0 = __shfl_up_sync(0xffffffffu, i0, 1); if (lane == 0) e0 = 0.0;
    double e1 = __shfl_up_sync(0xffffffffu, i1, 1); if (lane == 0) e1 = 0.0;
    e0 += s_chp[0][w];
    e1 += s_chp[1][w];
    const double sf2 = i2 + s_chs[0][w];
    const double sf3 = i3 + s_chs[1][w];

    g_tab[b][d][t][0] = make_double2(e0, e1);
    g_tab[b][d][t][1] = make_double2(sf2, sf3);
    if (t == M_ - 1) g_tab[b][d][M_][0] = make_double2(e0 + v0, e1 + v1);
    if (t == 0)      g_tab[b][d][M_][1] = make_double2(0.0, 0.0);
}

// fp64 * fp32 -> fp32 without the fp64 mul pipe: hi/lo split.
__device__ __forceinline__ float dmulf(double a, float s) {
    const float h = (float)a;
    const float l = (float)(a - (double)h);
    return fmaf(h, s, l * s);
}

// ---------------------------------------------------------------------------
// Kernel 3: expand fp64 k-tables into the fine fp32 bucket table.
// grid = 6 * EXPB_ blocks of 256.
// ---------------------------------------------------------------------------
__global__ void __launch_bounds__(256)
expand_kernel() {
    const int bd    = blockIdx.x / EXPB_;
    const int chunk = blockIdx.x % EXPB_;
    const int b = bd / D_, d = bd % D_;
    const int tid = threadIdx.x;

    __shared__ float s_dv[M_];
    #pragma unroll
    for (int i = tid; i < M_; i += 256) s_dv[i] = g_skey[b][d][i];
    __syncthreads();

    const int q = chunk * 256 + tid;
    if (q > LUT_) return;

    // Per-b common geometry (bitwise identical recomputation in eval).
    const float2 r0 = g_rngd[b][0], r1 = g_rngd[b][1], r2 = g_rngd[b][2];
    const float lo = fminf(r0.x, fminf(r1.x, r2.x));
    const float hi = fmaxf(r0.y, fmaxf(r1.y, r2.y));
    const float span = (hi - lo) * 1.0001f + 1e-20f;   // margin: e_LUT > hi strictly
    const float w = span * (1.0f / (float)LUT_);

    const float eq = fmaf((float)q, w, lo);

    // k = count(dv < eq).
    int k;
    if (s_dv[M_ - 1] < eq) {
        k = M_;
    } else {
        k = 0;
        #pragma unroll
        for (int s = M_ / 2; s >= 1; s >>= 1)
            if (s_dv[k + s - 1] < eq) k += s;
    }

    const double2 tp = g_tab[b][d][k][0];
    const double2 ts = g_tab[b][d][k][1];
    const float sm = expf(-4.0f * eq);
    const float sp = expf( 4.0f * eq);

    float4 o;
    o.x = dmulf(tp.x, sm);   // P   = sum_{dv<eq} e^{4(dv-eq)}      (O(1..1e3))
    o.y = dmulf(tp.y, sm);   // PM
    o.z = dmulf(ts.x, sp);   // S   = sum_{dv>=eq} e^{-4(dv-eq)}
    o.w = dmulf(ts.y, sp);   // SM
    g_ftab[b][d][q] = o;
}

// ---------------------------------------------------------------------------
// Kernel 4: eval. One thread per output: 1 LDG.128 + ~15 fp32 ops.
// out = (e*PM + SM)/(e*P + S), e = e^{-8(x - e_q)} ~= 1 - 8t off clamp path.
// Clamp paths are exact (one side empty => e cancels).
// grid = 768 blocks of 256.
// ---------------------------------------------------------------------------
__global__ void __launch_bounds__(256)
eval_kernel(const float* __restrict__ x, float* __restrict__ out) {
    const int gid = blockIdx.x * 256 + threadIdx.x;
    const int b = gid / (N_ * D_);
    const int d = gid % D_;

    const float2 r0 = g_rngd[b][0], r1 = g_rngd[b][1], r2 = g_rngd[b][2];
    const float lo = fminf(r0.x, fminf(r1.x, r2.x));
    const float hi = fmaxf(r0.y, fmaxf(r1.y, r2.y));
    const float span = (hi - lo) * 1.0001f + 1e-20f;
    const float w    = span * (1.0f / (float)LUT_);
    const float invw = (float)LUT_ / span;

    const float xv = x[gid];
    const float fq = (xv - lo) * invw;
    const int qi = (int)fq;
    const int q = qi < 0 ? 0 : (qi > LUT_ ? LUT_ : qi);

    const float4 tb = __ldg(&g_ftab[b][d][q]);
    const float t = xv - fmaf((float)q, w, lo);
    const float arg = -8.0f * t;
    const bool fast = (qi >= 0) & (qi < LUT_);
    const float e = fast ? (1.0f + arg) : __expf(arg);

    out[gid] = __fdividef(fmaf(e, tb.y, tb.w), fmaf(e, tb.x, tb.z));
}

// ---------------------------------------------------------------------------
extern "C" void kernel_launch(void* const* d_in, const int* in_sizes, int n_in,
                              void* d_out, int out_size) {
    const float* x  = (const float*)d_in[0];
    const float* dv = (const float*)d_in[1];
    const float* mv = (const float*)d_in[2];

    rank_kernel<<<B_ * D_ * SLICES_, 128>>>(dv, mv);
    scan_kernel<<<B_ * D_, M_>>>();
    expand_kernel<<<B_ * D_ * EXPB_, 256>>>();
    eval_kernel<<<(B_ * N_ * D_) / 256, 256>>>(x, (float*)d_out);
}